// round 3
// baseline (speedup 1.0000x reference)
#include <cuda_runtime.h>

#define TW 64
#define TH 64
#define RY 8
#define RX 2
#define HALO 3
#define SW (TW + 6)       /* 70 */
#define SH (TH + 6)       /* 70 */
#define SSTRIDE 72
#define MAXVAL 10000.0f
#define PLANE 256

__global__ __launch_bounds__(256, 2)
void quad_morpho_kernel(const float* __restrict__ x,
                        const float* __restrict__ k1,
                        const float* __restrict__ k2,
                        const float* __restrict__ k3,
                        float* __restrict__ out)
{
    __shared__ float s[SH][SSTRIDE];

    const int plane = blockIdx.z;
    const int tx0 = blockIdx.x * TW;
    const int ty0 = blockIdx.y * TH;
    const float* xp = x + (size_t)plane * PLANE * PLANE;
    float* op = out + (size_t)plane * PLANE * PLANE;

    const int tid = threadIdx.x;

    // ---- Fill tile + halo. Halo / out-of-plane = -MAXVAL, exactly matching
    // the reference's constant padding. ----
    for (int i = tid; i < SH * SW; i += 256) {
        int r = i / SW;
        int c = i - r * SW;
        int gr = ty0 + r - HALO;
        int gc = tx0 + c - HALO;
        float v = -MAXVAL;
        if ((unsigned)gr < (unsigned)PLANE && (unsigned)gc < (unsigned)PLANE)
            v = __ldg(&xp[gr * PLANE + gc]);
        s[r][c] = v;
    }

    // ---- Weight table: w(dy,dx) = -(k1*dx^2 + 2*k2*dx*dy + k3*dy^2) / m
    // m = max of the quadratic form over the 7x7 grid. Form is convex along
    // every axis-parallel line (k1,k3 >= 0) so max is at a corner. ----
    const float A = k1[0];
    const float B = k2[0];
    const float C = k3[0];
    const float q_pp = A * 9.0f + 2.0f * B * 9.0f + C * 9.0f;     // (dx,dy)=(3,3)
    const float q_pm = A * 9.0f + 2.0f * B * (-9.0f) + C * 9.0f;  // (3,-3)
    const float inv_m = 1.0f / fmaxf(q_pp, q_pm);
    const float nA = -A * inv_m, nB = -2.0f * B * inv_m, nC = -C * inv_m;

    float w[7][7];
#pragma unroll
    for (int dy = -3; dy <= 3; dy++) {
#pragma unroll
        for (int dx = -3; dx <= 3; dx++) {
            w[dy + 3][dx + 3] = nA * (float)(dx * dx)
                              + nB * (float)(dx * dy)
                              + nC * (float)(dy * dy);
        }
    }

    __syncthreads();

    // ---- Register-blocked compute: each thread produces RY x RX outputs. ----
    const int txg = tid & 31;        // 0..31 -> output col pair
    const int tyg = tid >> 5;        // 0..7  -> output row group
    const int oc   = txg * RX;       // tile-local output col base (even)
    const int orow = tyg * RY;       // tile-local output row base

    float acc0[RY], acc1[RY];
#pragma unroll
    for (int j = 0; j < RY; j++) { acc0[j] = -3.0e38f; acc1[j] = -3.0e38f; }

#pragma unroll
    for (int r = 0; r < RY + 6; r++) {
        // smem row (orow + r), cols oc .. oc+7 (oc even -> float2 aligned,
        // warp covers 64 consecutive floats -> conflict-free LDS.64)
        const float* row = &s[orow + r][oc];
        float2 p0 = *(const float2*)(row + 0);
        float2 p1 = *(const float2*)(row + 2);
        float2 p2 = *(const float2*)(row + 4);
        float2 p3 = *(const float2*)(row + 6);
        float v[8];
        v[0] = p0.x; v[1] = p0.y; v[2] = p1.x; v[3] = p1.y;
        v[4] = p2.x; v[5] = p2.y; v[6] = p3.x; v[7] = p3.y;

#pragma unroll
        for (int j = 0; j < RY; j++) {
            const int dy = r - j - 3;
            if (dy < -3 || dy > 3) continue;
#pragma unroll
            for (int t = 0; t < 7; t++) {
                if (dy == 0 && t == 3) continue;   // center tap excluded
                const float wv = w[dy + 3][t];
                acc0[j] = fmaxf(acc0[j], v[t]     + wv);
                acc1[j] = fmaxf(acc1[j], v[t + 1] + wv);
            }
        }
    }

    // ---- Store: float2 per row (aligned: tx0 multiple of 64, oc even). ----
#pragma unroll
    for (int j = 0; j < RY; j++) {
        float2 o2 = make_float2(acc0[j], acc1[j]);
        *(float2*)&op[(ty0 + orow + j) * PLANE + tx0 + oc] = o2;
    }
}

extern "C" void kernel_launch(void* const* d_in, const int* in_sizes, int n_in,
                              void* d_out, int out_size)
{
    const float* x  = (const float*)d_in[0];
    const float* k1 = (const float*)d_in[1];
    const float* k2 = (const float*)d_in[2];
    const float* k3 = (const float*)d_in[3];
    float* out = (float*)d_out;

    (void)in_sizes; (void)n_in; (void)out_size;

    dim3 block(256, 1, 1);
    dim3 grid(PLANE / TW, PLANE / TH, 8 * 64);
    quad_morpho_kernel<<<grid, block>>>(x, k1, k2, k3, out);
}

// round 6
// speedup vs baseline: 1.2626x; 1.2626x over previous
#include <cuda_runtime.h>

#define TW 64
#define TH 64
#define RY 8
#define RX 2
#define HALO 3
#define SW (TW + 6)       /* 70 */
#define SH (TH + 6)       /* 70 */
#define SSTRIDE 72
#define MAXVAL 10000.0f
#define PLANE 256

// Process one contiguous dy-group [DYLO, DYHI]. Only (DYHI-DYLO+1)*7 weight
// registers are live at a time, keeping total pressure ~50 regs so 4-5 CTAs
// fit per SM (vs 3 with the full 49-weight table).
template<int DYLO, int DYHI>
__device__ __forceinline__ void process_group(const float (*s)[SSTRIDE],
                                              int orow, int oc,
                                              float nA, float nB, float nC,
                                              float acc0[RY], float acc1[RY])
{
    constexpr int NW = DYHI - DYLO + 1;
    float w[NW][7];
#pragma unroll
    for (int d = 0; d < NW; d++) {
        const int dy = DYLO + d;
#pragma unroll
        for (int t = 0; t < 7; t++) {
            const int dx = t - 3;
            w[d][t] = nA * (float)(dx * dx)
                    + nB * (float)(dx * dy)
                    + nC * (float)(dy * dy);
        }
    }

    // Tile-local row offsets touched by this group:
    //   output j (0..7) with dy in [DYLO,DYHI] reads row orow + 3 + j + dy
#pragma unroll
    for (int R = DYLO + 3; R <= DYHI + 3 + RY - 1; R++) {
        const float* row = &s[orow + R][oc];
        float2 p0 = *(const float2*)(row + 0);
        float2 p1 = *(const float2*)(row + 2);
        float2 p2 = *(const float2*)(row + 4);
        float2 p3 = *(const float2*)(row + 6);
        float v[8];
        v[0] = p0.x; v[1] = p0.y; v[2] = p1.x; v[3] = p1.y;
        v[4] = p2.x; v[5] = p2.y; v[6] = p3.x; v[7] = p3.y;

#pragma unroll
        for (int j = 0; j < RY; j++) {
            const int dy = R - 3 - j;
            if (dy < DYLO || dy > DYHI) continue;
            const int d = dy - DYLO;
#pragma unroll
            for (int t = 0; t < 7; t++) {
                if (dy == 0 && t == 3) continue;   // center tap excluded
                const float wv = w[d][t];
                acc0[j] = fmaxf(acc0[j], v[t]     + wv);
                acc1[j] = fmaxf(acc1[j], v[t + 1] + wv);
            }
        }
    }
}

__global__ __launch_bounds__(256, 4)
void quad_morpho_kernel(const float* __restrict__ x,
                        const float* __restrict__ k1,
                        const float* __restrict__ k2,
                        const float* __restrict__ k3,
                        float* __restrict__ out)
{
    __shared__ float s[SH][SSTRIDE];

    const int plane = blockIdx.z;
    const int tx0 = blockIdx.x * TW;
    const int ty0 = blockIdx.y * TH;
    const float* xp = x + (size_t)plane * PLANE * PLANE;
    float* op = out + (size_t)plane * PLANE * PLANE;

    const int tid = threadIdx.x;

    // ---- Fill tile + halo (halo = -MAXVAL, matching reference padding). ----
    for (int i = tid; i < SH * SW; i += 256) {
        int r = i / SW;
        int c = i - r * SW;
        int gr = ty0 + r - HALO;
        int gc = tx0 + c - HALO;
        float v = -MAXVAL;
        if ((unsigned)gr < (unsigned)PLANE && (unsigned)gc < (unsigned)PLANE)
            v = __ldg(&xp[gr * PLANE + gc]);
        s[r][c] = v;
    }

    // ---- SE coefficients. max over 7x7 grid of the convex-along-axes
    // quadratic form is at a corner: (3,3) or (3,-3). ----
    const float A = k1[0];
    const float B = k2[0];
    const float C = k3[0];
    const float q_pp = A * 9.0f + 2.0f * B * 9.0f + C * 9.0f;
    const float q_pm = A * 9.0f + 2.0f * B * (-9.0f) + C * 9.0f;
    const float inv_m = 1.0f / fmaxf(q_pp, q_pm);
    const float nA = -A * inv_m, nB = -2.0f * B * inv_m, nC = -C * inv_m;

    __syncthreads();

    const int txg = tid & 31;        // 0..31 -> output col pair
    const int tyg = tid >> 5;        // 0..7  -> output row group
    const int oc   = txg * RX;       // tile-local output col base (even)
    const int orow = tyg * RY;       // tile-local output row base

    float acc0[RY], acc1[RY];
#pragma unroll
    for (int j = 0; j < RY; j++) { acc0[j] = -3.0e38f; acc1[j] = -3.0e38f; }

    // Three dy-groups, <=21 weight registers live each.
    process_group<-3, -2>(s, orow, oc, nA, nB, nC, acc0, acc1);
    process_group<-1,  1>(s, orow, oc, nA, nB, nC, acc0, acc1);
    process_group< 2,  3>(s, orow, oc, nA, nB, nC, acc0, acc1);

    // ---- Store: float2 per row (tx0 multiple of 64, oc even -> aligned). ----
#pragma unroll
    for (int j = 0; j < RY; j++) {
        float2 o2 = make_float2(acc0[j], acc1[j]);
        *(float2*)&op[(ty0 + orow + j) * PLANE + tx0 + oc] = o2;
    }
}

extern "C" void kernel_launch(void* const* d_in, const int* in_sizes, int n_in,
                              void* d_out, int out_size)
{
    const float* x  = (const float*)d_in[0];
    const float* k1 = (const float*)d_in[1];
    const float* k2 = (const float*)d_in[2];
    const float* k3 = (const float*)d_in[3];
    float* out = (float*)d_out;

    (void)in_sizes; (void)n_in; (void)out_size;

    dim3 block(256, 1, 1);
    dim3 grid(PLANE / TW, PLANE / TH, 8 * 64);
    quad_morpho_kernel<<<grid, block>>>(x, k1, k2, k3, out);
}

// round 10
// speedup vs baseline: 1.6101x; 1.2753x over previous
#include <cuda_runtime.h>
#include <cuda_fp16.h>

#define TW 64
#define TH 64
#define HALO 3
#define PKROWS 66         /* packed rows: pk[r] = (row r, row r+4), r in 0..65 */
#define SW 70
#define SSTRIDE 72
#define MAXVAL 10000.0f
#define PLANE 256

// Process dy-group [DYLO,DYHI]. Lanes of every half2 are output rows (j, j+4):
// identical (dy,dx) per lane -> broadcast weights, pre-packed operands.
template<int DYLO, int DYHI>
__device__ __forceinline__ void process_group(const __half2 (*pk)[SSTRIDE],
                                              int orow, int oc,
                                              float nA, float nB, float nC,
                                              __half2 acc0[4], __half2 acc1[4])
{
    constexpr int NW = DYHI - DYLO + 1;
    __half2 w[NW][7];
#pragma unroll
    for (int d = 0; d < NW; d++) {
        const int dy = DYLO + d;
#pragma unroll
        for (int t = 0; t < 7; t++) {
            const int dx = t - 3;
            float wv = nA * (float)(dx * dx)
                     + nB * (float)(dx * dy)
                     + nC * (float)(dy * dy);
            w[d][t] = __float2half2_rn(wv);
        }
    }

    // acc index j (0..3) with dy in group reads packed row orow + j + dy + 3.
#pragma unroll
    for (int R = DYLO + 3; R <= DYHI + 3 + 3; R++) {
        const __half2* row = &pk[orow + R][oc];
        // 8 half2 = 32B, oc even -> 8B-aligned: 4x LDS.64, conflict-free
        float2 q0 = *(const float2*)(row + 0);
        float2 q1 = *(const float2*)(row + 2);
        float2 q2 = *(const float2*)(row + 4);
        float2 q3 = *(const float2*)(row + 6);
        __half2 v[8];
        v[0] = *(__half2*)&q0.x; v[1] = *(__half2*)&q0.y;
        v[2] = *(__half2*)&q1.x; v[3] = *(__half2*)&q1.y;
        v[4] = *(__half2*)&q2.x; v[5] = *(__half2*)&q2.y;
        v[6] = *(__half2*)&q3.x; v[7] = *(__half2*)&q3.y;

#pragma unroll
        for (int j = 0; j < 4; j++) {
            const int dy = R - 3 - j;
            if (dy < DYLO || dy > DYHI) continue;
            const int d = dy - DYLO;
#pragma unroll
            for (int t = 0; t < 7; t++) {
                if (dy == 0 && t == 3) continue;   // center tap excluded (both lanes)
                const __half2 wv = w[d][t];
                acc0[j] = __hmax2(acc0[j], __hadd2(v[t],     wv));
                acc1[j] = __hmax2(acc1[j], __hadd2(v[t + 1], wv));
            }
        }
    }
}

__global__ __launch_bounds__(256, 4)
void quad_morpho_kernel(const float* __restrict__ x,
                        const float* __restrict__ k1,
                        const float* __restrict__ k2,
                        const float* __restrict__ k3,
                        float* __restrict__ out)
{
    __shared__ __half2 pk[PKROWS][SSTRIDE];

    const int plane = blockIdx.z;
    const int tx0 = blockIdx.x * TW;
    const int ty0 = blockIdx.y * TH;
    const float* xp = x + (size_t)plane * PLANE * PLANE;
    float* op = out + (size_t)plane * PLANE * PLANE;

    const int tid = threadIdx.x;

    // ---- Fill packed tile: pk[r][c] = (x[r-3], x[r+1]) at col c-3, halo=-MAXVAL.
    // Second load of the same row hits L1 (row r's lane1 == row r+4's lane0). ----
    for (int i = tid; i < PKROWS * SW; i += 256) {
        int r = i / SW;
        int c = i - r * SW;
        int gc  = tx0 + c - HALO;
        int gr0 = ty0 + r - HALO;
        int gr1 = gr0 + 4;
        float f0 = -MAXVAL, f1 = -MAXVAL;
        bool cin = (unsigned)gc < (unsigned)PLANE;
        if (cin && (unsigned)gr0 < (unsigned)PLANE) f0 = __ldg(&xp[gr0 * PLANE + gc]);
        if (cin && (unsigned)gr1 < (unsigned)PLANE) f1 = __ldg(&xp[gr1 * PLANE + gc]);
        pk[r][c] = __floats2half2_rn(f0, f1);
    }

    // ---- SE coefficients (fp32, matching reference normalization). Max of the
    // convex-along-axes form over the 7x7 grid is at corner (3,3) or (3,-3). ----
    const float A = k1[0];
    const float B = k2[0];
    const float C = k3[0];
    const float q_pp = A * 9.0f + 2.0f * B * 9.0f + C * 9.0f;
    const float q_pm = A * 9.0f + 2.0f * B * (-9.0f) + C * 9.0f;
    const float inv_m = 1.0f / fmaxf(q_pp, q_pm);
    const float nA = -A * inv_m, nB = -2.0f * B * inv_m, nC = -C * inv_m;

    __syncthreads();

    const int txg = tid & 31;        // 0..31 -> output column pair
    const int tyg = tid >> 5;        // 0..7  -> output row group
    const int oc   = txg * 2;        // tile-local col base (even)
    const int orow = tyg * 8;        // tile-local row base; rows orow..orow+7
                                     // handled as half2 lanes (j, j+4)

    __half2 acc0[4], acc1[4];
    const __half2 NEG = __float2half2_rn(-60000.0f);
#pragma unroll
    for (int j = 0; j < 4; j++) { acc0[j] = NEG; acc1[j] = NEG; }

    process_group<-3, -2>(pk, orow, oc, nA, nB, nC, acc0, acc1);
    process_group<-1,  1>(pk, orow, oc, nA, nB, nC, acc0, acc1);
    process_group< 2,  3>(pk, orow, oc, nA, nB, nC, acc0, acc1);

    // ---- Store: lane0 -> row orow+j, lane1 -> row orow+j+4; float2 per row. ----
#pragma unroll
    for (int j = 0; j < 4; j++) {
        int r0 = ty0 + orow + j;
        int cg = tx0 + oc;
        float2 lo = make_float2(__low2float(acc0[j]),  __low2float(acc1[j]));
        float2 hi = make_float2(__high2float(acc0[j]), __high2float(acc1[j]));
        *(float2*)&op[r0 * PLANE + cg]       = lo;
        *(float2*)&op[(r0 + 4) * PLANE + cg] = hi;
    }
}

extern "C" void kernel_launch(void* const* d_in, const int* in_sizes, int n_in,
                              void* d_out, int out_size)
{
    const float* x  = (const float*)d_in[0];
    const float* k1 = (const float*)d_in[1];
    const float* k2 = (const float*)d_in[2];
    const float* k3 = (const float*)d_in[3];
    float* out = (float*)d_out;

    (void)in_sizes; (void)n_in; (void)out_size;

    dim3 block(256, 1, 1);
    dim3 grid(PLANE / TW, PLANE / TH, 8 * 64);
    quad_morpho_kernel<<<grid, block>>>(x, k1, k2, k3, out);
}

// round 11
// speedup vs baseline: 2.3795x; 1.4778x over previous
#include <cuda_runtime.h>
#include <cuda_fp16.h>

#define PLANE 256
#define TW 64
#define TH 64
#define PKROWS 66          /* packed rows: pk[r] lanes = (row r-3, row r+1) rel ty0 */
#define SSTRIDE 72         /* half2 per packed row; 288B, 16B-aligned rows */
#define NQ 18              /* column quads per row (72/4) */
#define MAXVAL 10000.0f

__device__ __forceinline__ __half2 h2_from_u32(unsigned u) {
    __half2 h; *(unsigned*)&h = u; return h;
}

// Process dy-group [DYLO,DYHI]. Weights come from smem (broadcast LDS), only
// (DYHI-DYLO+1)*7 weight regs live. acc[j][c]: j = output row offset {0,1},
// lanes = rows (y, y+4); c = column 0..3.
template<int DYLO, int DYHI>
__device__ __forceinline__ void pgroup(const __half2 (*pk)[SSTRIDE],
                                       const __half2* wsh,
                                       int orow, int oc,
                                       __half2 acc[2][4])
{
    constexpr int NW = DYHI - DYLO + 1;
    __half2 w[NW][7];
#pragma unroll
    for (int d = 0; d < NW; d++)
#pragma unroll
        for (int t = 0; t < 7; t++)
            w[d][t] = wsh[(DYLO + d + 3) * 7 + t];   // broadcast, conflict-free

#pragma unroll
    for (int Rr = DYLO + 3; Rr <= DYHI + 4; Rr++) {
        // 12 half2 window, 16B-aligned (oc mult of 4, row stride 288B)
        const uint4* rp = (const uint4*)&pk[orow + Rr][oc];
        uint4 u0 = rp[0], u1 = rp[1], u2 = rp[2];
        __half2 v[12];
        v[0] = h2_from_u32(u0.x); v[1]  = h2_from_u32(u0.y);
        v[2] = h2_from_u32(u0.z); v[3]  = h2_from_u32(u0.w);
        v[4] = h2_from_u32(u1.x); v[5]  = h2_from_u32(u1.y);
        v[6] = h2_from_u32(u1.z); v[7]  = h2_from_u32(u1.w);
        v[8] = h2_from_u32(u2.x); v[9]  = h2_from_u32(u2.y);
        v[10]= h2_from_u32(u2.z); v[11] = h2_from_u32(u2.w);

#pragma unroll
        for (int j = 0; j < 2; j++) {
            const int dy = Rr - 3 - j;
            if (dy < DYLO || dy > DYHI) continue;
            const int d = dy - DYLO;
#pragma unroll
            for (int t = 0; t < 7; t++) {
                if (dy == 0 && t == 3) continue;      // center tap excluded
                const __half2 wv = w[d][t];
#pragma unroll
                for (int c = 0; c < 4; c++)
                    acc[j][c] = __hmax2(acc[j][c], __hadd2(v[c + t + 1], wv));
            }
        }
    }
}

__global__ __launch_bounds__(256, 4)
void quad_morpho_kernel(const float* __restrict__ x,
                        const float* __restrict__ k1,
                        const float* __restrict__ k2,
                        const float* __restrict__ k3,
                        float* __restrict__ out)
{
    __shared__ alignas(16) __half2 pk[PKROWS][SSTRIDE];
    __shared__ __half2 wsh[49];

    const int plane = blockIdx.z;
    const int tx0 = blockIdx.x * TW;
    const int ty0 = blockIdx.y * TH;
    const float* xp = x + (size_t)plane * (PLANE * PLANE);
    float* op = out + (size_t)plane * (PLANE * PLANE);
    const int tid = threadIdx.x;

    // ---- Weight table: computed once per block by 49 threads into smem.
    // Max of the convex-along-axes quadratic over the 7x7 grid is at a corner. ----
    if (tid < 49) {
        const float A = k1[0], B = k2[0], C = k3[0];
        const float q_pp = 9.0f * A + 18.0f * B + 9.0f * C;
        const float q_pm = 9.0f * A - 18.0f * B + 9.0f * C;
        const float inv_m = 1.0f / fmaxf(q_pp, q_pm);
        const int dy = tid / 7 - 3;
        const int dx = tid % 7 - 3;
        const float wv = -(A * (float)(dx * dx) + 2.0f * B * (float)(dx * dy)
                           + C * (float)(dy * dy)) * inv_m;
        wsh[tid] = __float2half2_rn(wv);
    }

    // ---- Packed tile fill. smem col c <-> global col tx0 + c - 4 (left halo 4
    // keeps quads 16B-aligned). pk[r][c] = half2(x[ty0+r-3], x[ty0+r+1]).
    // Fast path: aligned float4 loads; edge quads take predicated scalars. ----
    for (int i = tid; i < PKROWS * NQ; i += 256) {
        const int r = i / NQ;
        const int q = i - r * NQ;
        const int gc = tx0 + q * 4 - 4;
        const int gr0 = ty0 + r - 3;
        const int gr1 = gr0 + 4;
        const bool r0in = (unsigned)gr0 < PLANE;
        const bool r1in = (unsigned)gr1 < PLANE;
        float4 a = make_float4(-MAXVAL, -MAXVAL, -MAXVAL, -MAXVAL);
        float4 b = a;
        if (gc >= 0 && gc <= PLANE - 4) {
            if (r0in) a = *(const float4*)&xp[gr0 * PLANE + gc];
            if (r1in) b = *(const float4*)&xp[gr1 * PLANE + gc];
        } else {
            float* ap = &a.x; float* bp = &b.x;
#pragma unroll
            for (int e = 0; e < 4; e++) {
                const int gce = gc + e;
                if ((unsigned)gce < PLANE) {
                    if (r0in) ap[e] = xp[gr0 * PLANE + gce];
                    if (r1in) bp[e] = xp[gr1 * PLANE + gce];
                }
            }
        }
        __half2 h0 = __floats2half2_rn(a.x, b.x);
        __half2 h1 = __floats2half2_rn(a.y, b.y);
        __half2 h2v = __floats2half2_rn(a.z, b.z);
        __half2 h3 = __floats2half2_rn(a.w, b.w);
        uint4 st;
        st.x = *(unsigned*)&h0; st.y = *(unsigned*)&h1;
        st.z = *(unsigned*)&h2v; st.w = *(unsigned*)&h3;
        *(uint4*)&pk[r][q * 4] = st;       // 16B-aligned STS.128
    }
    __syncthreads();

    // ---- Thread tile: 4 columns x 2 row-pairs (rows y,y+1 and y+4,y+5). ----
    const int txg = tid & 15;
    const int tyg = tid >> 4;
    const int oc = txg * 4;                              // tile-local col base
    const int orow = 8 * (tyg >> 1) + 2 * (tyg & 1);     // tile-local row base

    __half2 acc[2][4];
    const __half2 NEG = __float2half2_rn(-60000.0f);
#pragma unroll
    for (int j = 0; j < 2; j++)
#pragma unroll
        for (int c = 0; c < 4; c++) acc[j][c] = NEG;

    pgroup<-3, -2>(pk, wsh, orow, oc, acc);
    pgroup<-1,  1>(pk, wsh, orow, oc, acc);
    pgroup< 2,  3>(pk, wsh, orow, oc, acc);

    // ---- Store: lane0 -> row y, lane1 -> row y+4; float4 per row (aligned). ----
#pragma unroll
    for (int j = 0; j < 2; j++) {
        const int y0 = ty0 + orow + j;
        const int cg = tx0 + oc;
        float4 lo, hi;
        lo.x = __low2float(acc[j][0]);  lo.y = __low2float(acc[j][1]);
        lo.z = __low2float(acc[j][2]);  lo.w = __low2float(acc[j][3]);
        hi.x = __high2float(acc[j][0]); hi.y = __high2float(acc[j][1]);
        hi.z = __high2float(acc[j][2]); hi.w = __high2float(acc[j][3]);
        *(float4*)&op[y0 * PLANE + cg]       = lo;
        *(float4*)&op[(y0 + 4) * PLANE + cg] = hi;
    }
}

extern "C" void kernel_launch(void* const* d_in, const int* in_sizes, int n_in,
                              void* d_out, int out_size)
{
    const float* x  = (const float*)d_in[0];
    const float* k1 = (const float*)d_in[1];
    const float* k2 = (const float*)d_in[2];
    const float* k3 = (const float*)d_in[3];
    float* out = (float*)d_out;

    (void)in_sizes; (void)n_in; (void)out_size;

    dim3 block(256, 1, 1);
    dim3 grid(PLANE / TW, PLANE / TH, 8 * 64);
    quad_morpho_kernel<<<grid, block>>>(x, k1, k2, k3, out);
}

// round 12
// speedup vs baseline: 2.6972x; 1.1335x over previous
#include <cuda_runtime.h>
#include <cuda_fp16.h>

#define PLANE 256
#define TW 64
#define TH 64
#define PKROWS 66          /* packed rows: pk[r] lanes = (row r-3, row r+1) rel ty0 */
#define SSTRIDE 72         /* half2 per packed row; 288B, 16B-aligned rows */
#define NQ 18              /* column quads per row (72/4) */
#define MAXVAL 10000.0f

__device__ __forceinline__ __half2 h2_from_u32(unsigned u) {
    __half2 h; *(unsigned*)&h = u; return h;
}

__device__ __forceinline__ void load_window(const __half2 (*pk)[SSTRIDE],
                                            int row, int oc, __half2 v[12])
{
    const uint4* rp = (const uint4*)&pk[row][oc];   // 16B-aligned, 3x LDS.128
    uint4 u0 = rp[0], u1 = rp[1], u2 = rp[2];
    v[0] = h2_from_u32(u0.x); v[1]  = h2_from_u32(u0.y);
    v[2] = h2_from_u32(u0.z); v[3]  = h2_from_u32(u0.w);
    v[4] = h2_from_u32(u1.x); v[5]  = h2_from_u32(u1.y);
    v[6] = h2_from_u32(u1.z); v[7]  = h2_from_u32(u1.w);
    v[8] = h2_from_u32(u2.x); v[9]  = h2_from_u32(u2.y);
    v[10]= h2_from_u32(u2.z); v[11] = h2_from_u32(u2.w);
}

// 7 taps with weight row w[t] (t increasing with dx), optional reversal
// (REV=1 uses w[6-t], exploiting w(dy,dx) = w(-dy,-dx)), optional center skip.
template<int REV, int SKIPC>
__device__ __forceinline__ void taps7(const __half2 v[12], const __half2 w[7],
                                      __half2 acc[4])
{
#pragma unroll
    for (int t = 0; t < 7; t++) {
        if (SKIPC && t == 3) continue;
        const __half2 wv = REV ? w[6 - t] : w[t];
#pragma unroll
        for (int c = 0; c < 4; c++)
            acc[c] = __hmax2(acc[c], __hadd2(v[c + t + 1], wv));
    }
}

// Outer dy group: |dy| in {2,3}. Weight rows for dy=-3,-2 are reused (t-reversed)
// for dy=+3,+2. Rows touched: Rr in {0,1,2} and {5,6,7}.
__device__ __forceinline__ void pgroup_outer(const __half2 (*pk)[SSTRIDE],
                                             const __half2* wsh,
                                             int orow, int oc,
                                             __half2 acc[2][4])
{
    __half2 w3[7], w2[7];
#pragma unroll
    for (int t = 0; t < 7; t++) w3[t] = wsh[0 * 7 + t];   // dy = -3
#pragma unroll
    for (int t = 0; t < 7; t++) w2[t] = wsh[1 * 7 + t];   // dy = -2
    __half2 v[12];

    // Rr = 0: j=0 dy=-3
    load_window(pk, orow + 0, oc, v);
    taps7<0,0>(v, w3, acc[0]);
    // Rr = 1: j=0 dy=-2 ; j=1 dy=-3
    load_window(pk, orow + 1, oc, v);
    taps7<0,0>(v, w2, acc[0]);
    taps7<0,0>(v, w3, acc[1]);
    // Rr = 2: j=1 dy=-2
    load_window(pk, orow + 2, oc, v);
    taps7<0,0>(v, w2, acc[1]);
    // Rr = 5: j=0 dy=+2
    load_window(pk, orow + 5, oc, v);
    taps7<1,0>(v, w2, acc[0]);
    // Rr = 6: j=0 dy=+3 ; j=1 dy=+2
    load_window(pk, orow + 6, oc, v);
    taps7<1,0>(v, w3, acc[0]);
    taps7<1,0>(v, w2, acc[1]);
    // Rr = 7: j=1 dy=+3
    load_window(pk, orow + 7, oc, v);
    taps7<1,0>(v, w3, acc[1]);
}

// Middle dy group: dy in {-1,0,1}. dy=+1 reuses dy=-1 row reversed.
// Rows touched: Rr in {2,3,4,5}.
__device__ __forceinline__ void pgroup_mid(const __half2 (*pk)[SSTRIDE],
                                           const __half2* wsh,
                                           int orow, int oc,
                                           __half2 acc[2][4])
{
    __half2 w1[7], w0[7];
#pragma unroll
    for (int t = 0; t < 7; t++) w1[t] = wsh[2 * 7 + t];   // dy = -1
#pragma unroll
    for (int t = 0; t < 7; t++) w0[t] = wsh[3 * 7 + t];   // dy =  0
    __half2 v[12];

    // Rr = 2: j=0 dy=-1
    load_window(pk, orow + 2, oc, v);
    taps7<0,0>(v, w1, acc[0]);
    // Rr = 3: j=0 dy=0 (skip center) ; j=1 dy=-1
    load_window(pk, orow + 3, oc, v);
    taps7<0,1>(v, w0, acc[0]);
    taps7<0,0>(v, w1, acc[1]);
    // Rr = 4: j=0 dy=+1 ; j=1 dy=0 (skip center)
    load_window(pk, orow + 4, oc, v);
    taps7<1,0>(v, w1, acc[0]);
    taps7<0,1>(v, w0, acc[1]);
    // Rr = 5: j=1 dy=+1
    load_window(pk, orow + 5, oc, v);
    taps7<1,0>(v, w1, acc[1]);
}

__global__ __launch_bounds__(256, 5)
void quad_morpho_kernel(const float* __restrict__ x,
                        const float* __restrict__ k1,
                        const float* __restrict__ k2,
                        const float* __restrict__ k3,
                        float* __restrict__ out)
{
    __shared__ alignas(16) __half2 pk[PKROWS][SSTRIDE];
    __shared__ __half2 wsh[28];   // rows: dy=-3,-2,-1,0

    const int plane = blockIdx.z;
    const int tx0 = blockIdx.x * TW;
    const int ty0 = blockIdx.y * TH;
    const float* xp = x + (size_t)plane * (PLANE * PLANE);
    float* op = out + (size_t)plane * (PLANE * PLANE);
    const int tid = threadIdx.x;

    // ---- Weight table (dy = -3..0 only; +dy rows are t-reversed mirrors).
    // Max of the convex-along-axes quadratic over the 7x7 grid is at a corner. ----
    if (tid < 28) {
        const float A = k1[0], B = k2[0], C = k3[0];
        const float q_pp = 9.0f * A + 18.0f * B + 9.0f * C;
        const float q_pm = 9.0f * A - 18.0f * B + 9.0f * C;
        const float inv_m = 1.0f / fmaxf(q_pp, q_pm);
        const int dy = tid / 7 - 3;          // -3..0
        const int dx = tid % 7 - 3;
        const float wv = -(A * (float)(dx * dx) + 2.0f * B * (float)(dx * dy)
                           + C * (float)(dy * dy)) * inv_m;
        wsh[tid] = __float2half2_rn(wv);
    }

    // ---- Packed tile fill. smem col c <-> global col tx0 + c - 4 (left halo 4
    // keeps quads 16B-aligned). pk[r][c] = half2(x[ty0+r-3], x[ty0+r+1]). ----
    for (int i = tid; i < PKROWS * NQ; i += 256) {
        const int r = i / NQ;
        const int q = i - r * NQ;
        const int gc = tx0 + q * 4 - 4;
        const int gr0 = ty0 + r - 3;
        const int gr1 = gr0 + 4;
        const bool r0in = (unsigned)gr0 < PLANE;
        const bool r1in = (unsigned)gr1 < PLANE;
        float4 a = make_float4(-MAXVAL, -MAXVAL, -MAXVAL, -MAXVAL);
        float4 b = a;
        if (gc >= 0 && gc <= PLANE - 4) {
            if (r0in) a = *(const float4*)&xp[gr0 * PLANE + gc];
            if (r1in) b = *(const float4*)&xp[gr1 * PLANE + gc];
        } else {
            float* ap = &a.x; float* bp = &b.x;
#pragma unroll
            for (int e = 0; e < 4; e++) {
                const int gce = gc + e;
                if ((unsigned)gce < PLANE) {
                    if (r0in) ap[e] = xp[gr0 * PLANE + gce];
                    if (r1in) bp[e] = xp[gr1 * PLANE + gce];
                }
            }
        }
        __half2 h0 = __floats2half2_rn(a.x, b.x);
        __half2 h1 = __floats2half2_rn(a.y, b.y);
        __half2 h2v = __floats2half2_rn(a.z, b.z);
        __half2 h3 = __floats2half2_rn(a.w, b.w);
        uint4 st;
        st.x = *(unsigned*)&h0; st.y = *(unsigned*)&h1;
        st.z = *(unsigned*)&h2v; st.w = *(unsigned*)&h3;
        *(uint4*)&pk[r][q * 4] = st;       // 16B-aligned STS.128
    }
    __syncthreads();

    // ---- Thread tile: 4 half2-columns x 2 row-pairs (rows y,y+1 & y+4,y+5). ----
    const int txg = tid & 15;
    const int tyg = tid >> 4;
    const int oc = txg * 4;                              // tile-local col base
    const int orow = 8 * (tyg >> 1) + 2 * (tyg & 1);     // tile-local row base

    __half2 acc[2][4];
    const __half2 NEG = __float2half2_rn(-60000.0f);
#pragma unroll
    for (int j = 0; j < 2; j++)
#pragma unroll
        for (int c = 0; c < 4; c++) acc[j][c] = NEG;

    pgroup_outer(pk, wsh, orow, oc, acc);
    pgroup_mid(pk, wsh, orow, oc, acc);

    // ---- Store: lane0 -> row y, lane1 -> row y+4; float4 per row (aligned). ----
#pragma unroll
    for (int j = 0; j < 2; j++) {
        const int y0 = ty0 + orow + j;
        const int cg = tx0 + oc;
        float4 lo, hi;
        lo.x = __low2float(acc[j][0]);  lo.y = __low2float(acc[j][1]);
        lo.z = __low2float(acc[j][2]);  lo.w = __low2float(acc[j][3]);
        hi.x = __high2float(acc[j][0]); hi.y = __high2float(acc[j][1]);
        hi.z = __high2float(acc[j][2]); hi.w = __high2float(acc[j][3]);
        *(float4*)&op[y0 * PLANE + cg]       = lo;
        *(float4*)&op[(y0 + 4) * PLANE + cg] = hi;
    }
}

extern "C" void kernel_launch(void* const* d_in, const int* in_sizes, int n_in,
                              void* d_out, int out_size)
{
    const float* x  = (const float*)d_in[0];
    const float* k1 = (const float*)d_in[1];
    const float* k2 = (const float*)d_in[2];
    const float* k3 = (const float*)d_in[3];
    float* out = (float*)d_out;

    (void)in_sizes; (void)n_in; (void)out_size;

    dim3 block(256, 1, 1);
    dim3 grid(PLANE / TW, PLANE / TH, 8 * 64);
    quad_morpho_kernel<<<grid, block>>>(x, k1, k2, k3, out);
}